// round 1
// baseline (speedup 1.0000x reference)
#include <cuda_runtime.h>
#include <cuda_bf16.h>
#include <mma.h>
#include <math.h>

using namespace nvcuda;

// Problem dims
#define B_   32
#define S_   64
#define T_   64
#define E_   256
#define H_   512
#define V_   32000
#define G3   1536   // 3*H

// ---------------------------------------------------------------------------
// Scratch (no allocation allowed -> __device__ globals)
// ---------------------------------------------------------------------------
__device__ __align__(256) float g_gi_enc[64 * 32 * G3];   // [t][b][3H]
__device__ __align__(256) float g_gi_dec[63 * 32 * G3];   // [t][b][3H]
__device__ __align__(256) float g_h[2 * 32 * H_];         // ping-pong encoder h
__device__ __align__(256) float g_HD[64 * 32 * H_];       // decoder states; row r=t*32+b; rows 2016..2047 zero pad

// ---------------------------------------------------------------------------
// init: zero out[:,0,:], zero h0, zero HD pad rows (HD[63])
// ---------------------------------------------------------------------------
__global__ void init_kernel(float* __restrict__ out, float* __restrict__ h0,
                            float* __restrict__ hd_pad) {
    int i = blockIdx.x * blockDim.x + threadIdx.x;
    if (i < B_ * V_) {
        int b = i / V_;
        int v = i - b * V_;
        out[(size_t)b * (T_ * (size_t)V_) + v] = 0.0f;           // out[b][0][v]
    } else if (i < B_ * V_ + B_ * H_) {
        h0[i - B_ * V_] = 0.0f;
    } else if (i < B_ * V_ + 2 * B_ * H_) {
        hd_pad[i - B_ * V_ - B_ * H_] = 0.0f;
    }
}

// ---------------------------------------------------------------------------
// gi = emb[seq] @ W_ih^T + b_ih     (gathered GEMM, fp32 SIMT)
// C[r][j], r = t*32 + b, token = seq[b*64 + t].  R rows, J = 1536, K = 256.
// Tile 64x64, 256 threads, 4x4 micro-tile.
// ---------------------------------------------------------------------------
__global__ void gi_gemm_kernel(const int* __restrict__ seq,
                               const float* __restrict__ emb,
                               const float* __restrict__ W_ih,
                               const float* __restrict__ b_ih,
                               float* __restrict__ gi, int R) {
    __shared__ float As[16][64];
    __shared__ float Bs[16][64];
    __shared__ int   toks[64];

    int tid = threadIdx.x;
    int r0 = blockIdx.y * 64;
    int j0 = blockIdx.x * 64;

    if (tid < 64) {
        int r = r0 + tid;
        int rr = (r < R) ? r : 0;
        toks[tid] = seq[(rr & 31) * 64 + (rr >> 5)];
    }
    __syncthreads();

    int ty = tid >> 4;          // 0..15 -> rows ty*4..ty*4+3
    int tx = tid & 15;          // 0..15 -> cols tx*4..tx*4+3
    float acc[4][4];
#pragma unroll
    for (int i = 0; i < 4; i++)
#pragma unroll
        for (int j = 0; j < 4; j++) acc[i][j] = 0.0f;

    int lr = tid & 63;          // loader row/col
    int kq = (tid >> 6) << 2;   // 0,4,8,12

    for (int kc = 0; kc < E_; kc += 16) {
        float4 av = *reinterpret_cast<const float4*>(emb + (size_t)toks[lr] * E_ + kc + kq);
        As[kq + 0][lr] = av.x; As[kq + 1][lr] = av.y;
        As[kq + 2][lr] = av.z; As[kq + 3][lr] = av.w;
        float4 bv = *reinterpret_cast<const float4*>(W_ih + (size_t)(j0 + lr) * E_ + kc + kq);
        Bs[kq + 0][lr] = bv.x; Bs[kq + 1][lr] = bv.y;
        Bs[kq + 2][lr] = bv.z; Bs[kq + 3][lr] = bv.w;
        __syncthreads();

#pragma unroll
        for (int kk = 0; kk < 16; kk++) {
            float4 a = *reinterpret_cast<const float4*>(&As[kk][ty << 2]);
            float4 b = *reinterpret_cast<const float4*>(&Bs[kk][tx << 2]);
            acc[0][0] = fmaf(a.x, b.x, acc[0][0]); acc[0][1] = fmaf(a.x, b.y, acc[0][1]);
            acc[0][2] = fmaf(a.x, b.z, acc[0][2]); acc[0][3] = fmaf(a.x, b.w, acc[0][3]);
            acc[1][0] = fmaf(a.y, b.x, acc[1][0]); acc[1][1] = fmaf(a.y, b.y, acc[1][1]);
            acc[1][2] = fmaf(a.y, b.z, acc[1][2]); acc[1][3] = fmaf(a.y, b.w, acc[1][3]);
            acc[2][0] = fmaf(a.z, b.x, acc[2][0]); acc[2][1] = fmaf(a.z, b.y, acc[2][1]);
            acc[2][2] = fmaf(a.z, b.z, acc[2][2]); acc[2][3] = fmaf(a.z, b.w, acc[2][3]);
            acc[3][0] = fmaf(a.w, b.x, acc[3][0]); acc[3][1] = fmaf(a.w, b.y, acc[3][1]);
            acc[3][2] = fmaf(a.w, b.z, acc[3][2]); acc[3][3] = fmaf(a.w, b.w, acc[3][3]);
        }
        __syncthreads();
    }

    int jb = j0 + (tx << 2);
    float4 bias = *reinterpret_cast<const float4*>(b_ih + jb);
#pragma unroll
    for (int i = 0; i < 4; i++) {
        int r = r0 + (ty << 2) + i;
        if (r < R) {
            float4 o;
            o.x = acc[i][0] + bias.x; o.y = acc[i][1] + bias.y;
            o.z = acc[i][2] + bias.z; o.w = acc[i][3] + bias.w;
            *reinterpret_cast<float4*>(gi + (size_t)r * G3 + jb) = o;
        }
    }
}

// ---------------------------------------------------------------------------
// One GRU step:  gh = h_prev @ W_hh^T + b_hh, then elementwise gate update.
// grid 128 CTAs (4 h-columns each), block 128 (warp = one column, lanes = batch).
// h_prev staged in SMEM [32][516] (pad 4 -> conflict-free float4 reads).
// ---------------------------------------------------------------------------
__global__ void gru_step_kernel(const float* __restrict__ gi_t,   // [32][1536]
                                const float* __restrict__ h_prev, // [32][512]
                                float* __restrict__ h_out,        // [32][512]
                                const float* __restrict__ W_hh,   // [1536][512]
                                const float* __restrict__ b_hh) { // [1536]
    extern __shared__ float h_s[];       // [32][516]
    int tid = threadIdx.x;

    const float4* hp4 = reinterpret_cast<const float4*>(h_prev);
#pragma unroll
    for (int i = tid; i < 32 * 128; i += 128) {
        float4 v = hp4[i];
        int b = i >> 7, k4 = (i & 127) << 2;
        *reinterpret_cast<float4*>(&h_s[b * 516 + k4]) = v;
    }
    __syncthreads();

    int b  = tid & 31;
    int cl = tid >> 5;
    int c  = blockIdx.x * 4 + cl;

    const float* wr = W_hh + (size_t)c * H_;
    const float* wz = W_hh + (size_t)(c + H_) * H_;
    const float* wn = W_hh + (size_t)(c + 2 * H_) * H_;
    const float* hb = h_s + b * 516;

    float ar0 = 0.f, ar1 = 0.f, az0 = 0.f, az1 = 0.f, an0 = 0.f, an1 = 0.f;
#pragma unroll 4
    for (int k = 0; k < H_; k += 8) {
        float4 ha = *reinterpret_cast<const float4*>(hb + k);
        float4 hc = *reinterpret_cast<const float4*>(hb + k + 4);
        float4 r0 = *reinterpret_cast<const float4*>(wr + k);
        float4 r1 = *reinterpret_cast<const float4*>(wr + k + 4);
        float4 z0 = *reinterpret_cast<const float4*>(wz + k);
        float4 z1 = *reinterpret_cast<const float4*>(wz + k + 4);
        float4 n0 = *reinterpret_cast<const float4*>(wn + k);
        float4 n1 = *reinterpret_cast<const float4*>(wn + k + 4);
        ar0 = fmaf(ha.x, r0.x, ar0); ar0 = fmaf(ha.y, r0.y, ar0);
        ar0 = fmaf(ha.z, r0.z, ar0); ar0 = fmaf(ha.w, r0.w, ar0);
        ar1 = fmaf(hc.x, r1.x, ar1); ar1 = fmaf(hc.y, r1.y, ar1);
        ar1 = fmaf(hc.z, r1.z, ar1); ar1 = fmaf(hc.w, r1.w, ar1);
        az0 = fmaf(ha.x, z0.x, az0); az0 = fmaf(ha.y, z0.y, az0);
        az0 = fmaf(ha.z, z0.z, az0); az0 = fmaf(ha.w, z0.w, az0);
        az1 = fmaf(hc.x, z1.x, az1); az1 = fmaf(hc.y, z1.y, az1);
        az1 = fmaf(hc.z, z1.z, az1); az1 = fmaf(hc.w, z1.w, az1);
        an0 = fmaf(ha.x, n0.x, an0); an0 = fmaf(ha.y, n0.y, an0);
        an0 = fmaf(ha.z, n0.z, an0); an0 = fmaf(ha.w, n0.w, an0);
        an1 = fmaf(hc.x, n1.x, an1); an1 = fmaf(hc.y, n1.y, an1);
        an1 = fmaf(hc.z, n1.z, an1); an1 = fmaf(hc.w, n1.w, an1);
    }

    float ghr = ar0 + ar1 + b_hh[c];
    float ghz = az0 + az1 + b_hh[c + H_];
    float ghn = an0 + an1 + b_hh[c + 2 * H_];

    const float* gib = gi_t + (size_t)b * G3;
    float gir = gib[c], giz = gib[c + H_], gin = gib[c + 2 * H_];

    float r = 1.0f / (1.0f + expf(-(gir + ghr)));
    float z = 1.0f / (1.0f + expf(-(giz + ghz)));
    float n = tanhf(gin + r * ghn);
    float hp = hb[c];
    h_out[(size_t)b * H_ + c] = (1.0f - z) * n + z * hp;
}

// ---------------------------------------------------------------------------
// Logits: C[2016 x 32000] = A[2016 x 512] @ W[32000 x 512]^T + bias,
// scattered into out[b][t+1][v]  (r = t*32 + b). tf32 wmma, fp32 accumulate.
// CTA tile 128x128, BK=32, 8 warps (2x4), warp tile 64x32.
// ---------------------------------------------------------------------------
__global__ void logits_kernel(const float* __restrict__ A,     // [2048][512], rows>=2016 zero
                              const float* __restrict__ W,     // [32000][512]
                              const float* __restrict__ bias,  // [32000]
                              float* __restrict__ out) {
    __shared__ float As[128][40];
    __shared__ float Bs[128][40];

    int tid = threadIdx.x;
    int wid = tid >> 5, lane = tid & 31;
    int m0 = blockIdx.y * 128;
    int n0 = blockIdx.x * 128;
    int wm = wid >> 2;   // 0..1
    int wn = wid & 3;    // 0..3

    wmma::fragment<wmma::accumulator, 16, 16, 8, float> c[4][2];
#pragma unroll
    for (int i = 0; i < 4; i++)
#pragma unroll
        for (int j = 0; j < 2; j++) wmma::fill_fragment(c[i][j], 0.0f);

    for (int kt = 0; kt < H_; kt += 32) {
#pragma unroll
        for (int i = tid; i < 1024; i += 256) {
            int m = i >> 3, kq = (i & 7) << 2;
            *reinterpret_cast<float4*>(&As[m][kq]) =
                *reinterpret_cast<const float4*>(&A[(size_t)(m0 + m) * H_ + kt + kq]);
            *reinterpret_cast<float4*>(&Bs[m][kq]) =
                *reinterpret_cast<const float4*>(&W[(size_t)(n0 + m) * H_ + kt + kq]);
        }
        __syncthreads();

#pragma unroll
        for (int kk = 0; kk < 32; kk += 8) {
            wmma::fragment<wmma::matrix_a, 16, 16, 8, wmma::precision::tf32, wmma::row_major> a[4];
            wmma::fragment<wmma::matrix_b, 16, 16, 8, wmma::precision::tf32, wmma::col_major> bf[2];
#pragma unroll
            for (int i = 0; i < 4; i++) {
                wmma::load_matrix_sync(a[i], &As[wm * 64 + i * 16][kk], 40);
#pragma unroll
                for (int e = 0; e < a[i].num_elements; e++)
                    a[i].x[e] = wmma::__float_to_tf32(a[i].x[e]);
            }
#pragma unroll
            for (int j = 0; j < 2; j++) {
                wmma::load_matrix_sync(bf[j], &Bs[wn * 32 + j * 16][kk], 40);
#pragma unroll
                for (int e = 0; e < bf[j].num_elements; e++)
                    bf[j].x[e] = wmma::__float_to_tf32(bf[j].x[e]);
            }
#pragma unroll
            for (int i = 0; i < 4; i++)
#pragma unroll
                for (int j = 0; j < 2; j++)
                    wmma::mma_sync(c[i][j], a[i], bf[j], c[i][j]);
        }
        __syncthreads();
    }

    // Epilogue: stage each 16x16 frag through SMEM (reuse As), add bias, scatter.
    float* buf = &As[0][0] + wid * 256;
#pragma unroll
    for (int i = 0; i < 4; i++) {
#pragma unroll
        for (int j = 0; j < 2; j++) {
            wmma::store_matrix_sync(buf, c[i][j], 16, wmma::mem_row_major);
            __syncwarp();
            int rBase = m0 + wm * 64 + i * 16;
            int vBase = n0 + wn * 32 + j * 16;
#pragma unroll
            for (int e = lane; e < 256; e += 32) {
                int rr = e >> 4, cc = e & 15;
                int r = rBase + rr;
                if (r < 2016) {
                    int v = vBase + cc;
                    out[(size_t)(r & 31) * (T_ * (size_t)V_) +
                        (size_t)((r >> 5) + 1) * V_ + v] = buf[e] + bias[v];
                }
            }
            __syncwarp();
        }
    }
}

// ---------------------------------------------------------------------------
// Host launcher
// ---------------------------------------------------------------------------
extern "C" void kernel_launch(void* const* d_in, const int* in_sizes, int n_in,
                              void* d_out, int out_size) {
    const int*   src      = (const int*)d_in[0];
    const int*   trg      = (const int*)d_in[1];
    const float* emb_enc  = (const float*)d_in[2];
    const float* W_ih_enc = (const float*)d_in[3];
    const float* W_hh_enc = (const float*)d_in[4];
    const float* b_ih_enc = (const float*)d_in[5];
    const float* b_hh_enc = (const float*)d_in[6];
    const float* emb_dec  = (const float*)d_in[7];
    const float* W_ih_dec = (const float*)d_in[8];
    const float* W_hh_dec = (const float*)d_in[9];
    const float* b_ih_dec = (const float*)d_in[10];
    const float* b_hh_dec = (const float*)d_in[11];
    const float* fc_W     = (const float*)d_in[12];
    const float* fc_b     = (const float*)d_in[13];
    float* out = (float*)d_out;

    float *gi_enc, *gi_dec, *hbuf, *HD;
    cudaGetSymbolAddress((void**)&gi_enc, g_gi_enc);
    cudaGetSymbolAddress((void**)&gi_dec, g_gi_dec);
    cudaGetSymbolAddress((void**)&hbuf,   g_h);
    cudaGetSymbolAddress((void**)&HD,     g_HD);

    const size_t SMEM_H = 32 * 516 * sizeof(float);   // 66048 B > 48KB
    cudaFuncSetAttribute(gru_step_kernel,
                         cudaFuncAttributeMaxDynamicSharedMemorySize, (int)SMEM_H);

    // zero out[:,0,:], h0, HD pad rows
    init_kernel<<<4128, 256>>>(out, hbuf, HD + (size_t)63 * 32 * H_);

    // input projections (hoisted out of recurrence)
    gi_gemm_kernel<<<dim3(24, 32), 256>>>(src, emb_enc, W_ih_enc, b_ih_enc, gi_enc, 64 * 32);
    gi_gemm_kernel<<<dim3(24, 32), 256>>>(trg, emb_dec, W_ih_dec, b_ih_dec, gi_dec, 63 * 32);

    // encoder recurrence (ping-pong h); final h_enc lands in hbuf[0]
    for (int t = 0; t < 64; t++) {
        gru_step_kernel<<<128, 128, SMEM_H>>>(
            gi_enc + (size_t)t * 32 * G3,
            hbuf + (size_t)(t & 1) * 32 * H_,
            hbuf + (size_t)((t + 1) & 1) * 32 * H_,
            W_hh_enc, b_hh_enc);
    }

    // decoder recurrence; states stored for batched logits GEMM
    for (int t = 0; t < 63; t++) {
        const float* hp = (t == 0) ? hbuf : (HD + (size_t)(t - 1) * 32 * H_);
        gru_step_kernel<<<128, 128, SMEM_H>>>(
            gi_dec + (size_t)t * 32 * G3, hp,
            HD + (size_t)t * 32 * H_,
            W_hh_dec, b_hh_dec);
    }

    // batched logits: [2016,512] @ [32000,512]^T + bias -> out[b][t+1][v]
    logits_kernel<<<dim3(250, 16), 256>>>(HD, fc_W, fc_b, out);
}

// round 3
// speedup vs baseline: 1.4930x; 1.4930x over previous
#include <cuda_runtime.h>
#include <cuda_bf16.h>
#include <mma.h>
#include <math.h>

using namespace nvcuda;

// Problem dims
#define B_   32
#define S_   64
#define T_   64
#define E_   256
#define H_   512
#define V_   32000
#define G3   1536   // 3*H

// ---------------------------------------------------------------------------
// Scratch (no allocation allowed -> __device__ globals)
// ---------------------------------------------------------------------------
__device__ __align__(256) float g_gi_enc[64 * 32 * G3];   // [t][b][3H]
__device__ __align__(256) float g_gi_dec[63 * 32 * G3];   // [t][b][3H]
__device__ __align__(256) float g_h[2 * 32 * H_];         // ping-pong encoder h
__device__ __align__(256) float g_HD[64 * 32 * H_];       // decoder states; row r=t*32+b; rows 2016..2047 zero pad
__device__ unsigned g_bar;                                 // grid barrier counter

// ---------------------------------------------------------------------------
// init: zero out[:,0,:], zero h0, zero HD pad rows (HD[63]), reset barrier
// ---------------------------------------------------------------------------
__global__ void init_kernel(float* __restrict__ out, float* __restrict__ h0,
                            float* __restrict__ hd_pad) {
    int i = blockIdx.x * blockDim.x + threadIdx.x;
    if (i == 0) g_bar = 0u;
    if (i < B_ * V_) {
        int b = i / V_;
        int v = i - b * V_;
        out[(size_t)b * (T_ * (size_t)V_) + v] = 0.0f;           // out[b][0][v]
    } else if (i < B_ * V_ + B_ * H_) {
        h0[i - B_ * V_] = 0.0f;
    } else if (i < B_ * V_ + 2 * B_ * H_) {
        hd_pad[i - B_ * V_ - B_ * H_] = 0.0f;
    }
}

// ---------------------------------------------------------------------------
// gi = emb[seq] @ W_ih^T + b_ih     (gathered GEMM, fp32 SIMT)
// ---------------------------------------------------------------------------
__global__ void gi_gemm_kernel(const int* __restrict__ seq,
                               const float* __restrict__ emb,
                               const float* __restrict__ W_ih,
                               const float* __restrict__ b_ih,
                               float* __restrict__ gi, int R) {
    __shared__ float As[16][64];
    __shared__ float Bs[16][64];
    __shared__ int   toks[64];

    int tid = threadIdx.x;
    int r0 = blockIdx.y * 64;
    int j0 = blockIdx.x * 64;

    if (tid < 64) {
        int r = r0 + tid;
        int rr = (r < R) ? r : 0;
        toks[tid] = seq[(rr & 31) * 64 + (rr >> 5)];
    }
    __syncthreads();

    int ty = tid >> 4;
    int tx = tid & 15;
    float acc[4][4];
#pragma unroll
    for (int i = 0; i < 4; i++)
#pragma unroll
        for (int j = 0; j < 4; j++) acc[i][j] = 0.0f;

    int lr = tid & 63;
    int kq = (tid >> 6) << 2;

    for (int kc = 0; kc < E_; kc += 16) {
        float4 av = *reinterpret_cast<const float4*>(emb + (size_t)toks[lr] * E_ + kc + kq);
        As[kq + 0][lr] = av.x; As[kq + 1][lr] = av.y;
        As[kq + 2][lr] = av.z; As[kq + 3][lr] = av.w;
        float4 bv = *reinterpret_cast<const float4*>(W_ih + (size_t)(j0 + lr) * E_ + kc + kq);
        Bs[kq + 0][lr] = bv.x; Bs[kq + 1][lr] = bv.y;
        Bs[kq + 2][lr] = bv.z; Bs[kq + 3][lr] = bv.w;
        __syncthreads();

#pragma unroll
        for (int kk = 0; kk < 16; kk++) {
            float4 a = *reinterpret_cast<const float4*>(&As[kk][ty << 2]);
            float4 b = *reinterpret_cast<const float4*>(&Bs[kk][tx << 2]);
            acc[0][0] = fmaf(a.x, b.x, acc[0][0]); acc[0][1] = fmaf(a.x, b.y, acc[0][1]);
            acc[0][2] = fmaf(a.x, b.z, acc[0][2]); acc[0][3] = fmaf(a.x, b.w, acc[0][3]);
            acc[1][0] = fmaf(a.y, b.x, acc[1][0]); acc[1][1] = fmaf(a.y, b.y, acc[1][1]);
            acc[1][2] = fmaf(a.y, b.z, acc[1][2]); acc[1][3] = fmaf(a.y, b.w, acc[1][3]);
            acc[2][0] = fmaf(a.z, b.x, acc[2][0]); acc[2][1] = fmaf(a.z, b.y, acc[2][1]);
            acc[2][2] = fmaf(a.z, b.z, acc[2][2]); acc[2][3] = fmaf(a.z, b.w, acc[2][3]);
            acc[3][0] = fmaf(a.w, b.x, acc[3][0]); acc[3][1] = fmaf(a.w, b.y, acc[3][1]);
            acc[3][2] = fmaf(a.w, b.z, acc[3][2]); acc[3][3] = fmaf(a.w, b.w, acc[3][3]);
        }
        __syncthreads();
    }

    int jb = j0 + (tx << 2);
    float4 bias = *reinterpret_cast<const float4*>(b_ih + jb);
#pragma unroll
    for (int i = 0; i < 4; i++) {
        int r = r0 + (ty << 2) + i;
        if (r < R) {
            float4 o;
            o.x = acc[i][0] + bias.x; o.y = acc[i][1] + bias.y;
            o.z = acc[i][2] + bias.z; o.w = acc[i][3] + bias.w;
            *reinterpret_cast<float4*>(gi + (size_t)r * G3 + jb) = o;
        }
    }
}

// ---------------------------------------------------------------------------
// Persistent GRU recurrence: encoder 64 steps + decoder 63 steps, ONE launch.
// 128 CTAs x 192 threads, all co-resident. Grid barrier between steps.
// Each CTA owns 4 h-columns (12 gh rows = 4 cols x 3 gates).
// W_hh rows cached in SMEM once per phase. h staged to SMEM each step (__ldcg).
// Warp = 32 lanes = 32 batches; warp w computes gh rows 2w, 2w+1.
// ---------------------------------------------------------------------------
#define NCTA 128

__device__ __forceinline__ void grid_barrier(unsigned target) {
    __syncthreads();
    if (threadIdx.x == 0) {
        __threadfence();                       // release h writes
        atomicAdd(&g_bar, 1u);
        volatile unsigned* p = &g_bar;
        while (*p < target) { __nanosleep(64); }
        __threadfence();                       // acquire other CTAs' writes
    }
    __syncthreads();
}

__device__ __forceinline__ float sigm(float x) {
    return 1.0f / (1.0f + __expf(-x));
}

__global__ __launch_bounds__(192, 1)
void gru_persist_kernel(const float* __restrict__ gi_enc,
                        const float* __restrict__ gi_dec,
                        float* __restrict__ hbuf,          // [2][32][512]
                        float* __restrict__ HD,            // [64][32][512]
                        const float* __restrict__ W_enc,   // [1536][512]
                        const float* __restrict__ b_enc,
                        const float* __restrict__ W_dec,
                        const float* __restrict__ b_dec) {
    extern __shared__ float smem[];
    float*  h_s  = smem;                 // [32][516] floats (float4 stride 129)
    float*  Ws   = smem + 16512;         // [12][512]
    float*  gh_s = smem + 16512 + 6144;  // [12][33]
    float4* h_s4 = reinterpret_cast<float4*>(h_s);
    float4* Ws4  = reinterpret_cast<float4*>(Ws);

    const int tid = threadIdx.x;
    const int b   = tid & 31;            // lane = batch
    const int w   = tid >> 5;            // warp 0..5
    const int cta = blockIdx.x;
    const int co  = w & 3;               // elementwise col offset (tid<128)
    const int c   = cta * 4 + co;        // global h column (tid<128)

    unsigned phase = 0;

    // ===================== encoder phase =====================
    // cache W_enc rows for this CTA: j -> global row (j>>2)*512 + cta*4 + (j&3)
    for (int idx = tid; idx < 12 * 128; idx += 192) {
        int j = idx >> 7, q = idx & 127;
        int row = (j >> 2) * 512 + cta * 4 + (j & 3);
        Ws4[j * 128 + q] = __ldg(reinterpret_cast<const float4*>(W_enc) + (size_t)row * 128 + q);
    }
    float br = 0.f, bz = 0.f, bn = 0.f;
    if (tid < 128) { br = b_enc[c]; bz = b_enc[c + 512]; bn = b_enc[c + 1024]; }
    __syncthreads();

    for (int t = 0; t < 64; t++) {
        const float4* hp4 = reinterpret_cast<const float4*>(hbuf + (t & 1) * 16384);
        float* hn = hbuf + ((t + 1) & 1) * 16384;

        // stage h_prev -> SMEM (L1 bypass: ping-pong buffer may be L1-stale)
        for (int i = tid; i < 4096; i += 192)
            h_s4[(i >> 7) * 129 + (i & 127)] = __ldcg(hp4 + i);
        __syncthreads();

        // gh = h_prev @ W^T for rows 2w, 2w+1
        {
            const int j0 = 2 * w, j1 = 2 * w + 1;
            const float4* hb = h_s4 + b * 129;
            const float4* w0 = Ws4 + j0 * 128;
            const float4* w1 = Ws4 + j1 * 128;
            float a00 = 0.f, a01 = 0.f, a10 = 0.f, a11 = 0.f;
#pragma unroll 4
            for (int q = 0; q < 128; q += 2) {
                float4 h0 = hb[q], h1 = hb[q + 1];
                float4 x0 = w0[q], x1 = w0[q + 1];
                float4 y0 = w1[q], y1 = w1[q + 1];
                a00 = fmaf(h0.x, x0.x, a00); a00 = fmaf(h0.y, x0.y, a00);
                a00 = fmaf(h0.z, x0.z, a00); a00 = fmaf(h0.w, x0.w, a00);
                a01 = fmaf(h1.x, x1.x, a01); a01 = fmaf(h1.y, x1.y, a01);
                a01 = fmaf(h1.z, x1.z, a01); a01 = fmaf(h1.w, x1.w, a01);
                a10 = fmaf(h0.x, y0.x, a10); a10 = fmaf(h0.y, y0.y, a10);
                a10 = fmaf(h0.z, y0.z, a10); a10 = fmaf(h0.w, y0.w, a10);
                a11 = fmaf(h1.x, y1.x, a11); a11 = fmaf(h1.y, y1.y, a11);
                a11 = fmaf(h1.z, y1.z, a11); a11 = fmaf(h1.w, y1.w, a11);
            }
            gh_s[j0 * 33 + b] = a00 + a01;
            gh_s[j1 * 33 + b] = a10 + a11;
        }
        __syncthreads();

        // gate update + write h_next
        if (tid < 128) {
            float ghr = gh_s[co * 33 + b] + br;
            float ghz = gh_s[(4 + co) * 33 + b] + bz;
            float ghn = gh_s[(8 + co) * 33 + b] + bn;
            const float* gib = gi_enc + (size_t)t * (32 * G3) + (size_t)b * G3;
            float r = sigm(__ldcg(gib + c) + ghr);
            float z = sigm(__ldcg(gib + c + 512) + ghz);
            float n = tanhf(__ldcg(gib + c + 1024) + r * ghn);
            float hp = h_s[b * 516 + c];
            hn[b * 512 + c] = (1.0f - z) * n + z * hp;
        }
        phase++;
        grid_barrier(phase * NCTA);
    }

    // ===================== decoder phase =====================
    for (int idx = tid; idx < 12 * 128; idx += 192) {
        int j = idx >> 7, q = idx & 127;
        int row = (j >> 2) * 512 + cta * 4 + (j & 3);
        Ws4[j * 128 + q] = __ldg(reinterpret_cast<const float4*>(W_dec) + (size_t)row * 128 + q);
    }
    if (tid < 128) { br = b_dec[c]; bz = b_dec[c + 512]; bn = b_dec[c + 1024]; }
    __syncthreads();

    for (int t = 0; t < 63; t++) {
        const float4* hp4 = reinterpret_cast<const float4*>(
            (t == 0) ? hbuf : (HD + (size_t)(t - 1) * 16384));
        float* hn = HD + (size_t)t * 16384;

        for (int i = tid; i < 4096; i += 192)
            h_s4[(i >> 7) * 129 + (i & 127)] = __ldcg(hp4 + i);
        __syncthreads();

        {
            const int j0 = 2 * w, j1 = 2 * w + 1;
            const float4* hb = h_s4 + b * 129;
            const float4* w0 = Ws4 + j0 * 128;
            const float4* w1 = Ws4 + j1 * 128;
            float a00 = 0.f, a01 = 0.f, a10 = 0.f, a11 = 0.f;
#pragma unroll 4
            for (int q = 0; q < 128; q += 2) {
                float4 h0 = hb[q], h1 = hb[q + 1];
                float4 x0 = w0[q], x1 = w0[q + 1];
                float4 y0 = w1[q], y1 = w1[q + 1];
                a00 = fmaf(h0.x, x0.x, a00); a00 = fmaf(h0.y, x0.y, a00);
                a00 = fmaf(h0.z, x0.z, a00); a00 = fmaf(h0.w, x0.w, a00);
                a01 = fmaf(h1.x, x1.x, a01); a01 = fmaf(h1.y, x1.y, a01);
                a01 = fmaf(h1.z, x1.z, a01); a01 = fmaf(h1.w, x1.w, a01);
                a10 = fmaf(h0.x, y0.x, a10); a10 = fmaf(h0.y, y0.y, a10);
                a10 = fmaf(h0.z, y0.z, a10); a10 = fmaf(h0.w, y0.w, a10);
                a11 = fmaf(h1.x, y1.x, a11); a11 = fmaf(h1.y, y1.y, a11);
                a11 = fmaf(h1.z, y1.z, a11); a11 = fmaf(h1.w, y1.w, a11);
            }
            gh_s[j0 * 33 + b] = a00 + a01;
            gh_s[j1 * 33 + b] = a10 + a11;
        }
        __syncthreads();

        if (tid < 128) {
            float ghr = gh_s[co * 33 + b] + br;
            float ghz = gh_s[(4 + co) * 33 + b] + bz;
            float ghn = gh_s[(8 + co) * 33 + b] + bn;
            const float* gib = gi_dec + (size_t)t * (32 * G3) + (size_t)b * G3;
            float r = sigm(__ldcg(gib + c) + ghr);
            float z = sigm(__ldcg(gib + c + 512) + ghz);
            float n = tanhf(__ldcg(gib + c + 1024) + r * ghn);
            float hp = h_s[b * 516 + c];
            hn[b * 512 + c] = (1.0f - z) * n + z * hp;
        }
        phase++;
        grid_barrier(phase * NCTA);
    }
}

// ---------------------------------------------------------------------------
// Logits: C[2016 x 32000] = A[2016 x 512] @ W[32000 x 512]^T + bias
// tf32 wmma, fp32 accumulate. CTA tile 128x128, BK=32, 8 warps.
// ---------------------------------------------------------------------------
__global__ void logits_kernel(const float* __restrict__ A,     // [2048][512], rows>=2016 zero
                              const float* __restrict__ W,     // [32000][512]
                              const float* __restrict__ bias,  // [32000]
                              float* __restrict__ out) {
    __shared__ float As[128][40];
    __shared__ float Bs[128][40];

    int tid = threadIdx.x;
    int wid = tid >> 5, lane = tid & 31;
    int m0 = blockIdx.y * 128;
    int n0 = blockIdx.x * 128;
    int wm = wid >> 2;
    int wn = wid & 3;

    wmma::fragment<wmma::accumulator, 16, 16, 8, float> c[4][2];
#pragma unroll
    for (int i = 0; i < 4; i++)
#pragma unroll
        for (int j = 0; j < 2; j++) wmma::fill_fragment(c[i][j], 0.0f);

    for (int kt = 0; kt < H_; kt += 32) {
#pragma unroll
        for (int i = tid; i < 1024; i += 256) {
            int m = i >> 3, kq = (i & 7) << 2;
            *reinterpret_cast<float4*>(&As[m][kq]) =
                *reinterpret_cast<const float4*>(&A[(size_t)(m0 + m) * H_ + kt + kq]);
            *reinterpret_cast<float4*>(&Bs[m][kq]) =
                *reinterpret_cast<const float4*>(&W[(size_t)(n0 + m) * H_ + kt + kq]);
        }
        __syncthreads();

#pragma unroll
        for (int kk = 0; kk < 32; kk += 8) {
            wmma::fragment<wmma::matrix_a, 16, 16, 8, wmma::precision::tf32, wmma::row_major> a[4];
            wmma::fragment<wmma::matrix_b, 16, 16, 8, wmma::precision::tf32, wmma::col_major> bf[2];
#pragma unroll
            for (int i = 0; i < 4; i++) {
                wmma::load_matrix_sync(a[i], &As[wm * 64 + i * 16][kk], 40);
#pragma unroll
                for (int e = 0; e < a[i].num_elements; e++)
                    a[i].x[e] = wmma::__float_to_tf32(a[i].x[e]);
            }
#pragma unroll
            for (int j = 0; j < 2; j++) {
                wmma::load_matrix_sync(bf[j], &Bs[wn * 32 + j * 16][kk], 40);
#pragma unroll
                for (int e = 0; e < bf[j].num_elements; e++)
                    bf[j].x[e] = wmma::__float_to_tf32(bf[j].x[e]);
            }
#pragma unroll
            for (int i = 0; i < 4; i++)
#pragma unroll
                for (int j = 0; j < 2; j++)
                    wmma::mma_sync(c[i][j], a[i], bf[j], c[i][j]);
        }
        __syncthreads();
    }

    float* buf = &As[0][0] + wid * 256;
#pragma unroll
    for (int i = 0; i < 4; i++) {
#pragma unroll
        for (int j = 0; j < 2; j++) {
            wmma::store_matrix_sync(buf, c[i][j], 16, wmma::mem_row_major);
            __syncwarp();
            int rBase = m0 + wm * 64 + i * 16;
            int vBase = n0 + wn * 32 + j * 16;
#pragma unroll
            for (int e = lane; e < 256; e += 32) {
                int rr = e >> 4, cc = e & 15;
                int r = rBase + rr;
                if (r < 2016) {
                    int v = vBase + cc;
                    out[(size_t)(r & 31) * (T_ * (size_t)V_) +
                        (size_t)((r >> 5) + 1) * V_ + v] = buf[e] + bias[v];
                }
            }
            __syncwarp();
        }
    }
}

// ---------------------------------------------------------------------------
// Host launcher
// ---------------------------------------------------------------------------
extern "C" void kernel_launch(void* const* d_in, const int* in_sizes, int n_in,
                              void* d_out, int out_size) {
    const int*   src      = (const int*)d_in[0];
    const int*   trg      = (const int*)d_in[1];
    const float* emb_enc  = (const float*)d_in[2];
    const float* W_ih_enc = (const float*)d_in[3];
    const float* W_hh_enc = (const float*)d_in[4];
    const float* b_ih_enc = (const float*)d_in[5];
    const float* b_hh_enc = (const float*)d_in[6];
    const float* emb_dec  = (const float*)d_in[7];
    const float* W_ih_dec = (const float*)d_in[8];
    const float* W_hh_dec = (const float*)d_in[9];
    const float* b_ih_dec = (const float*)d_in[10];
    const float* b_hh_dec = (const float*)d_in[11];
    const float* fc_W     = (const float*)d_in[12];
    const float* fc_b     = (const float*)d_in[13];
    float* out = (float*)d_out;

    float *gi_enc, *gi_dec, *hbuf, *HD;
    cudaGetSymbolAddress((void**)&gi_enc, g_gi_enc);
    cudaGetSymbolAddress((void**)&gi_dec, g_gi_dec);
    cudaGetSymbolAddress((void**)&hbuf,   g_h);
    cudaGetSymbolAddress((void**)&HD,     g_HD);

    const int SMEM_P = (16512 + 6144 + 12 * 33) * sizeof(float);  // 92208 B
    cudaFuncSetAttribute(gru_persist_kernel,
                         cudaFuncAttributeMaxDynamicSharedMemorySize, SMEM_P);

    // zero out[:,0,:], h0, HD pad rows, barrier counter
    init_kernel<<<4128, 256>>>(out, hbuf, HD + (size_t)63 * 32 * H_);

    // input projections (hoisted out of recurrence)
    gi_gemm_kernel<<<dim3(24, 32), 256>>>(src, emb_enc, W_ih_enc, b_ih_enc, gi_enc, 64 * 32);
    gi_gemm_kernel<<<dim3(24, 32), 256>>>(trg, emb_dec, W_ih_dec, b_ih_dec, gi_dec, 63 * 32);

    // entire recurrence (encoder + decoder) in ONE persistent launch
    gru_persist_kernel<<<NCTA, 192, SMEM_P>>>(gi_enc, gi_dec, hbuf, HD,
                                              W_hh_enc, b_hh_enc,
                                              W_hh_dec, b_hh_dec);

    // batched logits: [2016,512] @ [32000,512]^T + bias -> out[b][t+1][v]
    logits_kernel<<<dim3(250, 16), 256>>>(HD, fc_W, fc_b, out);
}